// round 9
// baseline (speedup 1.0000x reference)
#include <cuda_runtime.h>
#include <cuda_fp16.h>
#include <cstdint>

// Problem constants
#define NN 256
#define CC 64
#define TT 64
#define VV 22

// ---------------------------------------------------------------------------
// Device globals (scratch), fp16x2-packed words
// ---------------------------------------------------------------------------
// x2 padded: [n][t][w24(24)][cw(32)]; word cw holds ci pair
// ( (cw>>3)*16 + (cw&7),  (cw>>3)*16 + (cw&7) + 8 )
__device__ __align__(16) uint32_t g_x2ph[(size_t)NN * TT * 24 * 32];
// conv weights, co-major rows for ldmatrix: [j][co][32 k-pairs + 4 pad]
// word p holds (W[ci0], W[ci0+8]), ci0 = (p>>3)*16 + (p&7)   (matches g_x2ph)
__device__ __align__(16) uint32_t g_wshL[9 * 64 * 36];
// stage1 B fragments: [v][kc][lane][16 words]
__device__ __align__(16) uint32_t g_tphf[22 * 4 * 32 * 16];
// stage2 B fragments (Aeff): [q][lane][12 words] = [kc2][nt3][2 regs]
__device__ __align__(16) uint32_t g_b2f[64 * 32 * 12];

__device__ __forceinline__ void mma_fp16(float* c, const uint32_t* a,
                                         uint32_t b0, uint32_t b1) {
    asm volatile(
        "mma.sync.aligned.m16n8k16.row.col.f32.f16.f16.f32 "
        "{%0,%1,%2,%3}, {%4,%5,%6,%7}, {%8,%9}, {%0,%1,%2,%3};"
        : "+f"(c[0]), "+f"(c[1]), "+f"(c[2]), "+f"(c[3])
        : "r"(a[0]), "r"(a[1]), "r"(a[2]), "r"(a[3]), "r"(b0), "r"(b1));
}

__device__ __forceinline__ uint32_t pack2(float lo, float hi) {
    __half2 h = __floats2half2_rn(lo, hi);
    return *(uint32_t*)&h;
}

__device__ __forceinline__ uint32_t smaddr(const void* p) {
    return (uint32_t)__cvta_generic_to_shared(p);
}

__device__ __forceinline__ void ldmx4(uint32_t* r, uint32_t a) {
    asm volatile(
        "ldmatrix.sync.aligned.m8n8.x4.shared.b16 {%0,%1,%2,%3}, [%4];"
        : "=r"(r[0]), "=r"(r[1]), "=r"(r[2]), "=r"(r[3]) : "r"(a));
}

__device__ __forceinline__ void cp16(uint32_t dst, const void* src, int srcsz) {
    asm volatile("cp.async.ca.shared.global [%0], [%1], 16, %2;"
                 :: "r"(dst), "l"(src), "r"(srcsz) : "memory");
}

// ---------------------------------------------------------------------------
// Prep kernels
// ---------------------------------------------------------------------------
__global__ void prep_wshL(const float* __restrict__ Wc) {
    int i = blockIdx.x * 256 + threadIdx.x;
    if (i >= 9 * 64 * 32) return;
    int p  = i & 31;
    int co = (i >> 5) & 63;
    int j  = i >> 11;
    int ci0 = ((p >> 3) << 4) + (p & 7);      // pair (ci0, ci0+8)
    float w0 = Wc[co * 576 + ci0 * 9 + j];
    float w1 = Wc[co * 576 + (ci0 + 8) * 9 + j];
    g_wshL[j * 2304 + co * 36 + p] = pack2(w0, w1);
}

__global__ void prep_tphf(const float* __restrict__ Tp) {
    int i = blockIdx.x * 256 + threadIdx.x;
    if (i >= 22 * 4 * 32 * 16) return;
    int w    = i & 15;
    int lane = (i >> 4) & 31;
    int kc   = (i >> 9) & 3;
    int v    = i >> 11;
    int lg = lane >> 2, lk = lane & 3;
    int nt   = w & 7;
    int bsel = w >> 3;
    int P  = kc * 8 + lk + bsel * 4;
    int t0 = 2 * P;
    int q  = nt * 8 + lg;
    g_tphf[i] = pack2(Tp[v * 4096 + t0 * 64 + q],
                      Tp[v * 4096 + (t0 + 1) * 64 + q]);
}

__global__ void prep_b2f(const float* __restrict__ A,
                         const float* __restrict__ Afix) {
    int i = blockIdx.x * 256 + threadIdx.x;
    if (i >= 64 * 32 * 12) return;
    int w    = i % 12;
    int lane = (i / 12) & 31;
    int q    = i / (12 * 32);
    int kc = w / 6, rem = w - kc * 6;
    int nt = rem >> 1, r = rem & 1;
    int lg = lane >> 2, lk = lane & 3;
    int vp  = kc * 8 + lk + r * 4;      // v-pair index
    int w24 = nt * 8 + lg;
    int v0 = 2 * vp, v1 = 2 * vp + 1;
    float f0 = 0.f, f1 = 0.f;
    if (w24 >= 1 && w24 <= VV) {
        int ww = w24 - 1;
        if (v0 < VV) f0 = A[q * 484 + v0 * 22 + ww] + Afix[v0 * 22 + ww];
        if (v1 < VV) f1 = A[q * 484 + v1 * 22 + ww] + Afix[v1 * 22 + ww];
    }
    g_b2f[i] = pack2(f0, f1);
}

// ---------------------------------------------------------------------------
// Kernel 1: both einsums, fp16 m16n8k16. Block = (n, 16 channels), 256 thr.
// Stage 1 (unchanged): warp owns v-pair, writes x1 v-pairs into xout.
// Stage 2 (new orientation): C[c16, w24 24] = x1[c,v] * Aeff[v,w24] per q;
//   6 MMAs/q; output packs channel pairs (lg, lg+8) -> staged in smem (pin
//   reused) -> one fully-coalesced uint4 copy to g_x2ph.
// ---------------------------------------------------------------------------
#define PIN_WORDS (22 * 576)        // 12672 (>= 12288 staging)
#define XO_S 197
#define XO_WORDS (64 * XO_S)        // 12608
#define K1_SMEM ((PIN_WORDS + XO_WORDS) * 4)   // 101120

__global__ __launch_bounds__(256, 2)
void st_gcn_graph_fp16(const float* __restrict__ x)
{
    extern __shared__ uint32_t sm1[];
    uint32_t* pin  = sm1;
    uint32_t* xout = sm1 + PIN_WORDS;

    const int n    = blockIdx.y;
    const int cb   = blockIdx.x;
    const int c0   = cb * 16;
    const int tid  = threadIdx.x;
    const int warp = tid >> 5;
    const int lane = tid & 31;
    const int lg   = lane >> 2;
    const int lk   = lane & 3;

    // zero the 20 xout words per q that are read but never written
    for (int i = tid; i < 64 * 20; i += 256) {
        int q = i / 20, j = i - q * 20;
        int off = (j < 16) ? j * 12 + 11 : 192 + (j - 16);
        xout[q * XO_S + off] = 0;
    }

    // load x -> pin[(v*16+c)*36 + tp] = (x[c][2tp][v], x[c][2tp+1][v])
    const float* xb = x + ((size_t)n * CC + c0) * TT * VV;
    for (int i = tid; i < 16 * 32 * 11; i += 256) {
        int vp2 = i % 11;
        int r   = i / 11;
        int tp  = r & 31;
        int c   = r >> 5;
        float2 a = *((const float2*)(xb + (size_t)(c * 64 + 2 * tp) * 22) + vp2);
        float2 b = *((const float2*)(xb + (size_t)(c * 64 + 2 * tp + 1) * 22) + vp2);
        pin[((2 * vp2) * 16 + c) * 36 + tp]     = pack2(a.x, b.x);
        pin[((2 * vp2 + 1) * 16 + c) * 36 + tp] = pack2(a.y, b.y);
    }
    __syncthreads();

    const int arow  = (lane & 7) + ((lane >> 3) & 1) * 8;
    const int kword = (lane >> 4) * 4;
    const uint32_t pinA = smaddr(pin) + (arow * 36 + kword) * 4;

    // ---- Stage 1: v-pair GEMMs ----
    for (int pr = warp; pr < 11; pr += 8) {
        const int v0 = 2 * pr;
        uint32_t a0[4][4], a1[4][4];
        #pragma unroll
        for (int kc = 0; kc < 4; kc++) {
            ldmx4(a0[kc], pinA + (v0 * 576 + kc * 8) * 4);
            ldmx4(a1[kc], pinA + ((v0 + 1) * 576 + kc * 8) * 4);
        }
        #pragma unroll
        for (int pass = 0; pass < 2; pass++) {
            float acc0[4][4] = {}, acc1[4][4] = {};
            #pragma unroll
            for (int kc = 0; kc < 4; kc++) {
                const uint4* f0 = ((const uint4*)g_tphf) + ((v0 * 4 + kc) * 32 + lane) * 4;
                const uint4* f1 = f0 + 512;
                uint4 B00 = f0[pass], B01 = f0[2 + pass];
                uint4 B10 = f1[pass], B11 = f1[2 + pass];
                const uint32_t* w00 = (const uint32_t*)&B00;
                const uint32_t* w01 = (const uint32_t*)&B01;
                const uint32_t* w10 = (const uint32_t*)&B10;
                const uint32_t* w11 = (const uint32_t*)&B11;
                #pragma unroll
                for (int nt = 0; nt < 4; nt++) {
                    mma_fp16(acc0[nt], a0[kc], w00[nt], w01[nt]);
                    mma_fp16(acc1[nt], a1[kc], w10[nt], w11[nt]);
                }
            }
            #pragma unroll
            for (int nt = 0; nt < 4; nt++) {
                int q0 = (pass * 4 + nt) * 8 + 2 * lk;
                uint32_t* o = xout + q0 * XO_S + lg * 12 + pr;
                o[0]          = pack2(acc0[nt][0], acc1[nt][0]);
                o[XO_S]       = pack2(acc0[nt][1], acc1[nt][1]);
                o[96]         = pack2(acc0[nt][2], acc1[nt][2]);
                o[XO_S + 96]  = pack2(acc0[nt][3], acc1[nt][3]);
            }
        }
    }
    __syncthreads();   // stage1 done; pin is now dead -> reuse as staging

    // ---- Stage 2: C[c,w24] per q; warp owns 8 q; stage into pin ----
    {
        const uint4* bfb = ((const uint4*)g_b2f) + ((size_t)(warp * 8) * 32 + lane) * 3;
        uint4 B0 = bfb[0], B1 = bfb[1], B2 = bfb[2];
        #pragma unroll 1
        for (int qi = 0; qi < 8; qi++) {
            const int q = warp * 8 + qi;
            uint4 N0, N1, N2;
            if (qi < 7) {
                const uint4* nf = bfb + (qi + 1) * 96;
                N0 = nf[0]; N1 = nf[1]; N2 = nf[2];
            }
            const uint32_t* xq = xout + q * XO_S;
            uint32_t a[2][4];
            #pragma unroll
            for (int kc = 0; kc < 2; kc++) {
                a[kc][0] = xq[lg * 12 + kc * 8 + lk];
                a[kc][1] = xq[(lg + 8) * 12 + kc * 8 + lk];
                a[kc][2] = xq[lg * 12 + kc * 8 + lk + 4];
                a[kc][3] = xq[(lg + 8) * 12 + kc * 8 + lk + 4];
            }
            uint4 Bv[3] = {B0, B1, B2};
            const uint32_t* bw = (const uint32_t*)Bv;
            float acc[3][4] = {};
            #pragma unroll
            for (int kc = 0; kc < 2; kc++)
                #pragma unroll
                for (int nt = 0; nt < 3; nt++)
                    mma_fp16(acc[nt], a[kc], bw[kc * 6 + nt * 2],
                             bw[kc * 6 + nt * 2 + 1]);
            // stage: pin[q*192 + w24*8 + lg] = (C[lg], C[lg+8]) ci-pair word
            uint32_t* stq = pin + q * 192;
            #pragma unroll
            for (int nt = 0; nt < 3; nt++) {
                int w24a = nt * 8 + 2 * lk;
                stq[w24a * 8 + lg]       = pack2(acc[nt][0], acc[nt][2]);
                stq[(w24a + 1) * 8 + lg] = pack2(acc[nt][1], acc[nt][3]);
            }
            B0 = N0; B1 = N1; B2 = N2;
        }
    }
    __syncthreads();

    // coalesced copy-out: [q][w24][8 words] -> g_x2ph[n][q][w24][cb*8 + 0..7]
    {
        const uint4* s4 = (const uint4*)pin;
        uint4* dst = (uint4*)g_x2ph + (size_t)n * 12288 + cb * 2;
        for (int i = tid; i < 64 * 24 * 2; i += 256) {
            int u = i & 1, r = i >> 1;
            dst[(size_t)r * 8 + u] = s4[i];
        }
    }
}

// ---------------------------------------------------------------------------
// Kernel 2: persistent 3x3 conv, fp16 m16n8k16, weights resident in smem,
// cp.async double-buffered tiles, smem-staged coalesced epilogue.
// ---------------------------------------------------------------------------
#define CTC 16
#define CROWS 432                       // 18 t-rows x 24
#define WS_ALL (9 * 64 * 36)            // 20736 words
#define BUFW (CROWS * 36 + 72)          // 15624 words (>= 64*196 staging)
#define K2_SMEM ((WS_ALL + 2 * BUFW) * 4)   // 207936 B
#define NTILES (4 * NN)                 // 1024
#define NSM 148

__global__ __launch_bounds__(512, 1)
void st_gcn_conv_fp16(const float* __restrict__ x,
                      const float* __restrict__ bc,
                      float* __restrict__ y)
{
    extern __shared__ uint32_t sm2[];
    uint32_t* ws = sm2;
    const int tid = threadIdx.x;

    // Load ALL weights once
    {
        const uint4* src = (const uint4*)g_wshL;
        uint4* dst = (uint4*)ws;
        for (int i = tid; i < WS_ALL / 4; i += 512) dst[i] = src[i];
    }

    const int warp   = tid >> 5;
    const int lane   = tid & 31;
    const int lg     = lane >> 2;
    const int lk     = lane & 3;
    const int warp_m = warp >> 1;            // 0..7
    const int co0    = (warp & 1) * 32;
    const int m_base = warp_m * 48;

    const int arow  = (lane & 7) + ((lane >> 3) & 1) * 8;
    const int kword = (lane >> 4) * 4;
    const int g     = lane >> 3;
    const int bsel  = g >> 1;
    const int bcol  = (g & 1) * 4;
    const uint32_t wsb = smaddr(ws);
    uint32_t bBase[2];
    #pragma unroll
    for (int u = 0; u < 2; u++)
        bBase[u] = wsb + ((co0 + (u * 2 + bsel) * 8 + (lane & 7)) * 36 + bcol) * 4;

    const uint32_t smb = smaddr(sm2);

    auto fill = [&](int b, int tile) {
        const int n  = tile >> 2;
        const int t0 = (tile & 3) * CTC;
        const uint32_t dstb = smb + (WS_ALL + b * BUFW + 36) * 4;
        const uint4* srcn = (const uint4*)g_x2ph + ((size_t)n * TT * 24) * 8;
        for (int i = tid; i < CROWS * 8; i += 512) {
            int r = i >> 3, u = i & 7;
            int tr = r / 24;
            int w24 = r - tr * 24;
            int t = t0 - 1 + tr;
            bool ok = ((unsigned)t < (unsigned)TT);
            const uint4* src = srcn + (((size_t)(ok ? t : 0)) * 24 + w24) * 8 + u;
            cp16(dstb + (r * 36 + u * 4) * 4, src, ok ? 16 : 0);
        }
    };

    int tile = blockIdx.x;
    if (tile < NTILES) fill(0, tile);
    asm volatile("cp.async.commit_group;" ::: "memory");
    __syncthreads();   // weights visible

    int buf = 0;
    for (; tile < NTILES; tile += NSM) {
        int nxt = tile + NSM;
        if (nxt < NTILES) fill(buf ^ 1, nxt);
        asm volatile("cp.async.commit_group;" ::: "memory");
        asm volatile("cp.async.wait_group 1;" ::: "memory");
        __syncthreads();

        const int n  = tile >> 2;
        const int t0 = (tile & 3) * CTC;
        const uint32_t xtA = smb + (WS_ALL + buf * BUFW + 36) * 4
                             + (arow * 36 + kword) * 4;

        float acc[3][4][4] = {};
        #pragma unroll 3
        for (int j = 0; j < 9; j++) {
            const int roff = (j / 3) * 24 + (j % 3) - 1;
            const int mrow0 = m_base + roff;
            #pragma unroll
            for (int kc = 0; kc < 4; kc++) {
                uint32_t a[3][4];
                #pragma unroll
                for (int mt = 0; mt < 3; mt++)
                    ldmx4(a[mt], xtA + ((mrow0 + mt * 16) * 36 + kc * 8) * 4);
                #pragma unroll
                for (int u = 0; u < 2; u++) {
                    uint32_t bb[4];
                    ldmx4(bb, bBase[u] + (j * 2304 + kc * 8) * 4);
                    #pragma unroll
                    for (int mt = 0; mt < 3; mt++) {
                        mma_fp16(acc[mt][u * 2],     a[mt], bb[0], bb[1]);
                        mma_fp16(acc[mt][u * 2 + 1], a[mt], bb[2], bb[3]);
                    }
                }
            }
        }

        // ---- Epilogue: stage into just-consumed buf, coalesced write-out ---
        float* stage = (float*)(sm2 + WS_ALL + buf * BUFW);
        __syncthreads();   // all MMA reads of buf complete
        #pragma unroll 1
        for (int h = 0; h < 2; h++) {
            if ((warp >> 3) == h) {
                #pragma unroll
                for (int mt = 0; mt < 3; mt++) {
                    int plb = (warp_m - h * 4) * 48 + mt * 16 + lg;
                    #pragma unroll
                    for (int hf = 0; hf < 2; hf++) {
                        int pl = plb + hf * 8;
                        #pragma unroll
                        for (int nt = 0; nt < 4; nt++) {
                            int co = co0 + nt * 8 + 2 * lk;
                            stage[co * 196 + pl]       = acc[mt][nt][hf * 2];
                            stage[(co + 1) * 196 + pl] = acc[mt][nt][hf * 2 + 1];
                        }
                    }
                }
            }
            __syncthreads();
            const int tbase = t0 + h * 8;
            for (int i = tid; i < 2816; i += 512) {
                int co = i / 44;
                int g4 = i - co * 44;
                int f  = g4 * 4;
                size_t yb = (((size_t)n * CC + co) * TT + tbase) * VV + f;
                float4 xr = *(const float4*)(x + yb);
                float bcv = bc[co];
                float o[4];
                #pragma unroll
                for (int e = 0; e < 4; e++) {
                    int fe = f + e;
                    int tre = fe / 22;
                    int pl  = fe + 2 * tre + 1;   // skip pad cols 0/23
                    o[e] = stage[co * 196 + pl] + bcv;
                }
                float4 out = make_float4(o[0] + xr.x, o[1] + xr.y,
                                         o[2] + xr.z, o[3] + xr.w);
                *(float4*)(y + yb) = out;
            }
            __syncthreads();
        }
        buf ^= 1;
    }
}

// ---------------------------------------------------------------------------
// Launcher
// ---------------------------------------------------------------------------
extern "C" void kernel_launch(void* const* d_in, const int* in_sizes, int n_in,
                              void* d_out, int out_size)
{
    const float* x    = (const float*)d_in[0];
    const float* Tp   = (const float*)d_in[1];
    const float* A    = (const float*)d_in[2];
    const float* Afix = (const float*)d_in[3];
    const float* Wc   = (const float*)d_in[4];
    const float* bc   = (const float*)d_in[5];
    float* y = (float*)d_out;

    cudaFuncSetAttribute(st_gcn_graph_fp16,
                         cudaFuncAttributeMaxDynamicSharedMemorySize, K1_SMEM);
    cudaFuncSetAttribute(st_gcn_conv_fp16,
                         cudaFuncAttributeMaxDynamicSharedMemorySize, K2_SMEM);

    prep_wshL<<<(9 * 64 * 32 + 255) / 256, 256>>>(Wc);
    prep_tphf<<<(22 * 4 * 32 * 16 + 255) / 256, 256>>>(Tp);
    prep_b2f<<<(64 * 32 * 12 + 255) / 256, 256>>>(A, Afix);
    st_gcn_graph_fp16<<<dim3(4, NN), 256, K1_SMEM>>>(x);
    st_gcn_conv_fp16<<<NSM, 512, K2_SMEM>>>(x, bc, y);
}